// round 8
// baseline (speedup 1.0000x reference)
#include <cuda_runtime.h>
#include <math.h>

#define FIN 512
#define HD  16
#define CD  7
#define NMAX 100000
#define EMAX 3200000
#define TPB  256
#define XS   20      // smem words per node row (80B: 16B-aligned + conflict-free)

typedef unsigned long long u64;

// ---------------- scratch (static device globals) ----------------
__device__ int   g_cnt [NMAX];        // in-degree (w/o self-loop); re-zeroed by scan
__device__ int   g_rows[NMAX + 1];    // CSR row starts (+ total at [n])
__device__ int   g_cur [NMAX];        // fill cursor
__device__ int   g_bsum[128];         // scan block sums
__device__ float g_dinv[NMAX];
__device__ int   g_esrc[EMAX];        // CSR: source node per edge slot
__device__ float g_h1  [NMAX * HD];
__device__ float g_h2  [NMAX * 8];    // 7 classes padded to 8 (col7 == 0)
__device__ volatile int g_bar;        // scan barrier arrive counter
__device__ volatile int g_flag;       // scan barrier release flag
__device__ volatile int g_done;       // scan exit counter (self-reset)

// ---------------- f32x2 / cp.async helpers ----------------
__device__ __forceinline__ u64 pk2(float lo, float hi) {
    u64 r; asm("mov.b64 %0, {%1, %2};" : "=l"(r) : "f"(lo), "f"(hi)); return r;
}
__device__ __forceinline__ void upk2(float& lo, float& hi, u64 v) {
    asm("mov.b64 {%0, %1}, %2;" : "=f"(lo), "=f"(hi) : "l"(v));
}
__device__ __forceinline__ void fma2(u64& d, u64 a, u64 b) {
    asm("fma.rn.f32x2 %0, %1, %2, %0;" : "+l"(d) : "l"(a), "l"(b));
}
__device__ __forceinline__ unsigned su32(const void* p) {
    return (unsigned)__cvta_generic_to_shared(p);
}
__device__ __forceinline__ void cpa16(unsigned dst, const void* src) {
    asm volatile("cp.async.ca.shared.global [%0], [%1], 16;" :: "r"(dst), "l"(src));
}
__device__ __forceinline__ void cpa_commit() {
    asm volatile("cp.async.commit_group;");
}
template<int N> __device__ __forceinline__ void cpa_wait() {
    asm volatile("cp.async.wait_group %0;" :: "n"(N) : "memory");
}

// ---------------- GEMM1 smem layout ----------------
struct GSmem {
    float sX [2][256 * XS];   // node-major x subtile, double buffered (40KB)
    u64   sWt[2][8 * 16];     // k-pair-packed W: [kp][j], double buffered (2KB)
};

// stage subtile (16 k) for buffer buf: x via cp.async, W via LDG+STS (packed)
__device__ __forceinline__ void gemm_stage(GSmem* sm, int buf,
                                           const float* __restrict__ x,
                                           const float* __restrict__ W1,
                                           int n, int n0, int k0, int t) {
    int node = n0 + t;
    const float* src = (node < n) ? (x + (size_t)node * FIN + k0) : x;
    unsigned dst = su32(&sm->sX[buf][t * XS]);
    cpa16(dst,      src);
    cpa16(dst + 16, src + 4);
    cpa16(dst + 32, src + 8);
    cpa16(dst + 48, src + 12);
    if (t < 128) {                       // 16 j x 8 kp = 128
        int j  = t & 15;
        int kp = t >> 4;
        float we = W1[(size_t)(k0 + 2 * kp)     * HD + j];
        float wo = W1[(size_t)(k0 + 2 * kp + 1) * HD + j];
        sm->sWt[buf][kp * 16 + j] = pk2(we, wo);
    }
}

// ---------------- GEMM1 tile: 256 nodes x 16 cols ----------------
// Thread (ng=t>>2, jg=t&3): nodes {ng, ng+64, ng+128, ng+192} x cols jg*4..+3.
// f32x2 accumulators are packed over (even k, odd k); reduced lo+hi at end.
__device__ void gemm1_tile(const float* __restrict__ x,
                           const float* __restrict__ W1,
                           int n, int tile, GSmem* sm) {
    const int t  = threadIdx.x;
    const int n0 = tile * 256;
    const int ng = t >> 2;
    const int jg = t & 3;

    u64 acc[4][4];
#pragma unroll
    for (int p = 0; p < 4; p++)
#pragma unroll
        for (int c = 0; c < 4; c++) acc[p][c] = 0ull;

    gemm_stage(sm, 0, x, W1, n, n0, 0, t);
    cpa_commit();

#pragma unroll 1
    for (int s = 0; s < FIN / 16; s++) {
        int buf = s & 1;
        if (s + 1 < FIN / 16) {
            gemm_stage(sm, buf ^ 1, x, W1, n, n0, (s + 1) * 16, t);
            cpa_commit();
            cpa_wait<1>();
        } else {
            cpa_wait<0>();
        }
        __syncthreads();
#pragma unroll
        for (int kp = 0; kp < 8; kp++) {
            u64 x0 = *(const u64*)&sm->sX[buf][(ng      ) * XS + kp * 2];
            u64 x1 = *(const u64*)&sm->sX[buf][(ng +  64) * XS + kp * 2];
            u64 x2 = *(const u64*)&sm->sX[buf][(ng + 128) * XS + kp * 2];
            u64 x3 = *(const u64*)&sm->sX[buf][(ng + 192) * XS + kp * 2];
            const u64* wb = &sm->sWt[buf][kp * 16 + jg * 4];
            u64 w0 = wb[0], w1 = wb[1], w2 = wb[2], w3 = wb[3];
            fma2(acc[0][0], x0, w0); fma2(acc[0][1], x0, w1);
            fma2(acc[0][2], x0, w2); fma2(acc[0][3], x0, w3);
            fma2(acc[1][0], x1, w0); fma2(acc[1][1], x1, w1);
            fma2(acc[1][2], x1, w2); fma2(acc[1][3], x1, w3);
            fma2(acc[2][0], x2, w0); fma2(acc[2][1], x2, w1);
            fma2(acc[2][2], x2, w2); fma2(acc[2][3], x2, w3);
            fma2(acc[3][0], x3, w0); fma2(acc[3][1], x3, w1);
            fma2(acc[3][2], x3, w2); fma2(acc[3][3], x3, w3);
        }
        __syncthreads();
    }

#pragma unroll
    for (int p = 0; p < 4; p++) {
        int node = n0 + ng + 64 * p;
        if (node < n) {
            float r[4];
#pragma unroll
            for (int c = 0; c < 4; c++) {
                float lo, hi; upk2(lo, hi, acc[p][c]);
                r[c] = lo + hi;
            }
            *(float4*)&g_h1[(size_t)node * HD + jg * 4] =
                make_float4(r[0], r[1], r[2], r[3]);
        }
    }
}

// ---------------- launch A: degree count overlapped with GEMM part A ----------------

__global__ __launch_bounds__(TPB, 3) void kA(const int* __restrict__ dst, int e,
                                             const float* __restrict__ x,
                                             const float* __restrict__ W1, int n,
                                             int gemmBlocks) {
    __shared__ GSmem sm;
    if ((int)blockIdx.x < gemmBlocks) { gemm1_tile(x, W1, n, blockIdx.x, &sm); return; }
    int nb = gridDim.x - gemmBlocks;
    int b  = blockIdx.x - gemmBlocks;
    for (int i = b * TPB + threadIdx.x; i < e; i += nb * TPB)
        atomicAdd(&g_cnt[dst[i]], 1);
}

// ---------------- launch B: CSR fill overlapped with GEMM part B ----------------

__global__ __launch_bounds__(TPB, 3) void kB(const int* __restrict__ src,
                                             const int* __restrict__ dst, int e,
                                             const float* __restrict__ x,
                                             const float* __restrict__ W1, int n,
                                             int gemmBlocks, int gemmOffset) {
    __shared__ GSmem sm;
    if ((int)blockIdx.x < gemmBlocks) {
        gemm1_tile(x, W1, n, gemmOffset + blockIdx.x, &sm);
        return;
    }
    int nb = gridDim.x - gemmBlocks;
    int b  = blockIdx.x - gemmBlocks;
    for (int i = b * TPB + threadIdx.x; i < e; i += nb * TPB) {
        int s = src[i], d = dst[i];
        int pos = atomicAdd(&g_cur[d], 1);
        g_esrc[pos] = s;
    }
}

// ---------------- single-kernel scan (+rsqrt, +cnt re-zero, self-reset) ----------
// Grid must be <= 148 blocks (all resident). nb = ceil(n/1024) = 98 here.

__global__ __launch_bounds__(TPB) void k_scan_all(int n, int nb) {
    __shared__ int s[256];
    const int t = threadIdx.x;
    const int b = blockIdx.x;

    int base = b * 1024 + t * 4;
    int v0 = (base + 0 < n) ? g_cnt[base + 0] : 0;
    int v1 = (base + 1 < n) ? g_cnt[base + 1] : 0;
    int v2 = (base + 2 < n) ? g_cnt[base + 2] : 0;
    int v3 = (base + 3 < n) ? g_cnt[base + 3] : 0;
    if (base + 0 < n) g_dinv[base + 0] = rsqrtf((float)(v0 + 1));
    if (base + 1 < n) g_dinv[base + 1] = rsqrtf((float)(v1 + 1));
    if (base + 2 < n) g_dinv[base + 2] = rsqrtf((float)(v2 + 1));
    if (base + 3 < n) g_dinv[base + 3] = rsqrtf((float)(v3 + 1));
    int ts = v0 + v1 + v2 + v3;
    s[t] = ts;
    __syncthreads();
#pragma unroll
    for (int off = 1; off < 256; off <<= 1) {
        int xv = (t >= off) ? s[t - off] : 0;
        __syncthreads();
        s[t] += xv;
        __syncthreads();
    }
    int excl = s[t] - ts;

    if (t == 255) {
        g_bsum[b] = s[255];
        __threadfence();
        atomicAdd((int*)&g_bar, 1);
    }

    if (b == 0) {
        if (t == 0) {
            while (g_bar < nb) { }
            int acc2 = 0;
            for (int i = 0; i < nb; i++) { int v = g_bsum[i]; g_bsum[i] = acc2; acc2 += v; }
            g_rows[n] = acc2;
            __threadfence();
            g_flag = 1;
        }
        __syncthreads();
    } else {
        if (t == 0) {
            while (g_flag == 0) { }
            __threadfence();
        }
        __syncthreads();
    }

    int off = g_bsum[b];
    int r = excl + off;
    if (base + 0 < n) { g_rows[base + 0] = r; g_cur[base + 0] = r; g_cnt[base + 0] = 0; r += v0; }
    if (base + 1 < n) { g_rows[base + 1] = r; g_cur[base + 1] = r; g_cnt[base + 1] = 0; r += v1; }
    if (base + 2 < n) { g_rows[base + 2] = r; g_cur[base + 2] = r; g_cnt[base + 2] = 0; r += v2; }
    if (base + 3 < n) { g_rows[base + 3] = r; g_cur[base + 3] = r; g_cnt[base + 3] = 0; }

    __syncthreads();
    if (t == 0) {
        int d = atomicAdd((int*)&g_done, 1);
        if (d == nb - 1) { g_bar = 0; g_flag = 0; g_done = 0; }
    }
}

// ---------------- agg layer 1 + fused layer-2 transform ----------------
// 4 lanes per node; lane c owns feats [4c,4c+4). Unroll 4 for MLP.

__global__ __launch_bounds__(TPB) void k_agg1(const float* __restrict__ b1,
                                              const float* __restrict__ W2, int n) {
    __shared__ float sW2[HD * 8];
    __shared__ float sb1[HD];
    int t = threadIdx.x;
    if (t < HD * 8) {
        int j = t >> 3, cc = t & 7;
        sW2[t] = (cc < CD) ? W2[j * CD + cc] : 0.f;
    } else if (t < HD * 8 + HD) {
        sb1[t - HD * 8] = b1[t - HD * 8];
    }
    __syncthreads();

    int node = blockIdx.x * 64 + (t >> 2);
    int c = t & 3;
    bool valid = node < n;
    if (!valid) node = n - 1;

    float dv = g_dinv[node];
    float4 h = *(const float4*)(g_h1 + (size_t)node * HD + c * 4);
    float4 acc = make_float4(h.x * dv, h.y * dv, h.z * dv, h.w * dv);

    int st = g_rows[node];
    int cnt = g_rows[node + 1] - st;
    int j = 0;
    for (; j + 3 < cnt; j += 4) {
        int s0 = g_esrc[st + j],     s1 = g_esrc[st + j + 1];
        int s2 = g_esrc[st + j + 2], s3 = g_esrc[st + j + 3];
        float m0 = g_dinv[s0], m1 = g_dinv[s1], m2 = g_dinv[s2], m3 = g_dinv[s3];
        float4 w0 = *(const float4*)(g_h1 + (size_t)s0 * HD + c * 4);
        float4 w1 = *(const float4*)(g_h1 + (size_t)s1 * HD + c * 4);
        float4 w2 = *(const float4*)(g_h1 + (size_t)s2 * HD + c * 4);
        float4 w3 = *(const float4*)(g_h1 + (size_t)s3 * HD + c * 4);
        acc.x += w0.x * m0 + w1.x * m1 + w2.x * m2 + w3.x * m3;
        acc.y += w0.y * m0 + w1.y * m1 + w2.y * m2 + w3.y * m3;
        acc.z += w0.z * m0 + w1.z * m1 + w2.z * m2 + w3.z * m3;
        acc.w += w0.w * m0 + w1.w * m1 + w2.w * m2 + w3.w * m3;
    }
    for (; j < cnt; j++) {
        int s0 = g_esrc[st + j];
        float m0 = g_dinv[s0];
        float4 w0 = *(const float4*)(g_h1 + (size_t)s0 * HD + c * 4);
        acc.x += w0.x * m0; acc.y += w0.y * m0;
        acc.z += w0.z * m0; acc.w += w0.w * m0;
    }

    float q0 = fmaxf(acc.x * dv + sb1[c * 4 + 0], 0.f);
    float q1 = fmaxf(acc.y * dv + sb1[c * 4 + 1], 0.f);
    float q2 = fmaxf(acc.z * dv + sb1[c * 4 + 2], 0.f);
    float q3 = fmaxf(acc.w * dv + sb1[c * 4 + 3], 0.f);

    float p[8];
#pragma unroll
    for (int cc = 0; cc < 8; cc++) {
        p[cc] = q0 * sW2[(c * 4 + 0) * 8 + cc]
              + q1 * sW2[(c * 4 + 1) * 8 + cc]
              + q2 * sW2[(c * 4 + 2) * 8 + cc]
              + q3 * sW2[(c * 4 + 3) * 8 + cc];
    }
#pragma unroll
    for (int cc = 0; cc < 8; cc++) {
        p[cc] += __shfl_xor_sync(0xFFFFFFFFu, p[cc], 1);
        p[cc] += __shfl_xor_sync(0xFFFFFFFFu, p[cc], 2);
    }
    if (valid) {
        if (c == 0)
            *(float4*)(g_h2 + (size_t)node * 8)     = make_float4(p[0], p[1], p[2], p[3]);
        else if (c == 1)
            *(float4*)(g_h2 + (size_t)node * 8 + 4) = make_float4(p[4], p[5], p[6], 0.f);
    }
}

// ---------------- agg layer 2 + fused bias + log_softmax ----------------

__global__ __launch_bounds__(TPB) void k_agg2(const float* __restrict__ b2,
                                              float* __restrict__ out, int n) {
    __shared__ float sb2[8];
    int t = threadIdx.x;
    if (t < 8) sb2[t] = (t < CD) ? b2[t] : -1e30f;   // pad lane -> exp()==0
    __syncthreads();

    int node = blockIdx.x * 128 + (t >> 1);
    int c = t & 1;
    bool valid = node < n;
    if (!valid) node = n - 1;

    float dv = g_dinv[node];
    float4 h = *(const float4*)(g_h2 + (size_t)node * 8 + c * 4);
    float4 acc = make_float4(h.x * dv, h.y * dv, h.z * dv, h.w * dv);

    int st = g_rows[node];
    int cnt = g_rows[node + 1] - st;
    int j = 0;
    for (; j + 3 < cnt; j += 4) {
        int s0 = g_esrc[st + j],     s1 = g_esrc[st + j + 1];
        int s2 = g_esrc[st + j + 2], s3 = g_esrc[st + j + 3];
        float m0 = g_dinv[s0], m1 = g_dinv[s1], m2 = g_dinv[s2], m3 = g_dinv[s3];
        float4 w0 = *(const float4*)(g_h2 + (size_t)s0 * 8 + c * 4);
        float4 w1 = *(const float4*)(g_h2 + (size_t)s1 * 8 + c * 4);
        float4 w2 = *(const float4*)(g_h2 + (size_t)s2 * 8 + c * 4);
        float4 w3 = *(const float4*)(g_h2 + (size_t)s3 * 8 + c * 4);
        acc.x += w0.x * m0 + w1.x * m1 + w2.x * m2 + w3.x * m3;
        acc.y += w0.y * m0 + w1.y * m1 + w2.y * m2 + w3.y * m3;
        acc.z += w0.z * m0 + w1.z * m1 + w2.z * m2 + w3.z * m3;
        acc.w += w0.w * m0 + w1.w * m1 + w2.w * m2 + w3.w * m3;
    }
    for (; j < cnt; j++) {
        int s0 = g_esrc[st + j];
        float m0 = g_dinv[s0];
        float4 w0 = *(const float4*)(g_h2 + (size_t)s0 * 8 + c * 4);
        acc.x += w0.x * m0; acc.y += w0.y * m0;
        acc.z += w0.z * m0; acc.w += w0.w * m0;
    }

    float o0 = acc.x * dv + sb2[c * 4 + 0];
    float o1 = acc.y * dv + sb2[c * 4 + 1];
    float o2 = acc.z * dv + sb2[c * 4 + 2];
    float o3 = acc.w * dv + sb2[c * 4 + 3];

    float m = fmaxf(fmaxf(o0, o1), fmaxf(o2, o3));
    m = fmaxf(m, __shfl_xor_sync(0xFFFFFFFFu, m, 1));
    float s = expf(o0 - m) + expf(o1 - m) + expf(o2 - m) + expf(o3 - m);
    s += __shfl_xor_sync(0xFFFFFFFFu, s, 1);
    float l = m + logf(s);

    if (valid) {
        float* op = out + (size_t)node * CD + c * 4;
        op[0] = o0 - l; op[1] = o1 - l; op[2] = o2 - l;
        if (c == 0) op[3] = o3 - l;
    }
}

// ---------------- launch ----------------

extern "C" void kernel_launch(void* const* d_in, const int* in_sizes, int n_in,
                              void* d_out, int out_size) {
    const float* x  = (const float*)d_in[0];
    const int*   ei = (const int*)  d_in[1];
    const float* W1 = (const float*)d_in[2];
    const float* b1 = (const float*)d_in[3];
    const float* W2 = (const float*)d_in[4];
    const float* b2 = (const float*)d_in[5];

    const int n = in_sizes[0] / FIN;
    const int e = in_sizes[1] / 2;
    const int* src = ei;
    const int* dst = ei + e;

    const int NT = (n + 255) / 256;        // gemm tiles (391)
    const int GA = 120;                    // tiles in launch A (overlap degree count)
    const int GB = NT - GA;                // tiles in launch B (overlap CSR fill)
    const int nbScan = (n + 1023) / 1024;  // 98 <= 148 (must stay resident)

    kA         <<<GA + 240, TPB>>>(dst, e, x, W1, n, GA);
    k_scan_all <<<nbScan, TPB>>>(n, nbScan);
    kB         <<<GB + 173, TPB>>>(src, dst, e, x, W1, n, GB, GA);
    k_agg1     <<<(n + 63) / 64, TPB>>>(b1, W2, n);
    k_agg2     <<<(n + 127) / 128, TPB>>>(b2, (float*)d_out, n);
}

// round 9
// speedup vs baseline: 1.3573x; 1.3573x over previous
#include <cuda_runtime.h>
#include <math.h>

#define FIN 512
#define HD  16
#define CD  7
#define NMAX 100000
#define EMAX 3200000
#define TPB  256

typedef unsigned long long u64;

// ---------------- scratch (static device globals) ----------------
__device__ int   g_cnt [NMAX];        // in-degree (w/o self-loop); re-zeroed by scan
__device__ int   g_rows[NMAX + 1];    // CSR row starts (+ total at [n])
__device__ int   g_cur [NMAX];        // fill cursor
__device__ int   g_bsum[128];         // scan block sums
__device__ float g_dinv[NMAX];
__device__ int   g_esrc[EMAX];        // CSR: source node per edge slot
__device__ float g_h1  [NMAX * HD];
__device__ float g_h2  [NMAX * 8];    // 7 classes padded to 8 (col7 == 0)
__device__ volatile int g_bar;        // scan barrier arrive counter
__device__ volatile int g_flag;       // scan barrier release flag
__device__ volatile int g_done;       // scan exit counter (self-reset)

// ---------------- GEMM1: h1 = x @ W1 (exact round-1 kernel, 68.8us measured) ----
// Block = 256 threads computes a 256-node x 16-col tile.
// Thread (ng, jg): 4 nodes x 4 cols register micro-tile.
// x tile staged node-major with stride 33 (conflict-free STS and LDS).

__global__ __launch_bounds__(256) void k_gemm1(const float* __restrict__ x,
                                               const float* __restrict__ W1, int n) {
    __shared__ float4 sW[32 * 4];        // 32 k x 16 j
    __shared__ float  sX[256 * 33];      // 256 nodes x 32 k (+1 pad)

    const int t  = threadIdx.x;
    const int n0 = blockIdx.x * 256;
    const int ng = t >> 2;               // 0..63
    const int jg = t & 3;                // 0..3

    float acc[4][4];
#pragma unroll
    for (int a = 0; a < 4; a++)
#pragma unroll
        for (int b = 0; b < 4; b++) acc[a][b] = 0.0f;

    for (int k0 = 0; k0 < FIN; k0 += 32) {
        __syncthreads();
        if (t < 128) {
            sW[t] = *(const float4*)(W1 + (size_t)(k0 + (t >> 2)) * HD + (t & 3) * 4);
        }
#pragma unroll
        for (int i = 0; i < 8; i++) {
            int f    = t + 256 * i;
            int nl   = f >> 3;           // local node 0..255
            int kq   = f & 7;            // float4 index within 32-k row
            int node = n0 + nl;
            float4 v = make_float4(0.f, 0.f, 0.f, 0.f);
            if (node < n) v = *(const float4*)(x + (size_t)node * FIN + k0 + kq * 4);
            float* sp = &sX[nl * 33 + kq * 4];
            sp[0] = v.x; sp[1] = v.y; sp[2] = v.z; sp[3] = v.w;
        }
        __syncthreads();
#pragma unroll
        for (int k = 0; k < 32; k++) {
            float4 wv = sW[k * 4 + jg];
            float x0 = sX[(ng * 4 + 0) * 33 + k];
            float x1 = sX[(ng * 4 + 1) * 33 + k];
            float x2 = sX[(ng * 4 + 2) * 33 + k];
            float x3 = sX[(ng * 4 + 3) * 33 + k];
            acc[0][0] += x0 * wv.x; acc[0][1] += x0 * wv.y; acc[0][2] += x0 * wv.z; acc[0][3] += x0 * wv.w;
            acc[1][0] += x1 * wv.x; acc[1][1] += x1 * wv.y; acc[1][2] += x1 * wv.z; acc[1][3] += x1 * wv.w;
            acc[2][0] += x2 * wv.x; acc[2][1] += x2 * wv.y; acc[2][2] += x2 * wv.z; acc[2][3] += x2 * wv.w;
            acc[3][0] += x3 * wv.x; acc[3][1] += x3 * wv.y; acc[3][2] += x3 * wv.z; acc[3][3] += x3 * wv.w;
        }
    }
#pragma unroll
    for (int ni = 0; ni < 4; ni++) {
        int node = n0 + ng * 4 + ni;
        if (node < n)
            *(float4*)&g_h1[(size_t)node * HD + jg * 4] =
                make_float4(acc[ni][0], acc[ni][1], acc[ni][2], acc[ni][3]);
    }
}

// ---------------- degree count (g_cnt zeroed by previous replay's scan) ------

__global__ void k_cnt(const int* __restrict__ dst, int e) {
    int i = blockIdx.x * blockDim.x + threadIdx.x;
    if (i < e) atomicAdd(&g_cnt[dst[i]], 1);
}

// ---------------- single-kernel scan (+rsqrt, +cnt re-zero, self-reset) ------
// Grid must be <= 148 blocks (all resident). nb = ceil(n/1024) = 98 here.

__global__ __launch_bounds__(TPB) void k_scan_all(int n, int nb) {
    __shared__ int s[256];
    const int t = threadIdx.x;
    const int b = blockIdx.x;

    int base = b * 1024 + t * 4;
    int v0 = (base + 0 < n) ? g_cnt[base + 0] : 0;
    int v1 = (base + 1 < n) ? g_cnt[base + 1] : 0;
    int v2 = (base + 2 < n) ? g_cnt[base + 2] : 0;
    int v3 = (base + 3 < n) ? g_cnt[base + 3] : 0;
    if (base + 0 < n) g_dinv[base + 0] = rsqrtf((float)(v0 + 1));
    if (base + 1 < n) g_dinv[base + 1] = rsqrtf((float)(v1 + 1));
    if (base + 2 < n) g_dinv[base + 2] = rsqrtf((float)(v2 + 1));
    if (base + 3 < n) g_dinv[base + 3] = rsqrtf((float)(v3 + 1));
    int ts = v0 + v1 + v2 + v3;
    s[t] = ts;
    __syncthreads();
#pragma unroll
    for (int off = 1; off < 256; off <<= 1) {
        int xv = (t >= off) ? s[t - off] : 0;
        __syncthreads();
        s[t] += xv;
        __syncthreads();
    }
    int excl = s[t] - ts;

    if (t == 255) {
        g_bsum[b] = s[255];
        __threadfence();
        atomicAdd((int*)&g_bar, 1);
    }

    if (b == 0) {
        if (t == 0) {
            while (g_bar < nb) { }
            int acc2 = 0;
            for (int i = 0; i < nb; i++) { int v = g_bsum[i]; g_bsum[i] = acc2; acc2 += v; }
            g_rows[n] = acc2;
            __threadfence();
            g_flag = 1;
        }
        __syncthreads();
    } else {
        if (t == 0) {
            while (g_flag == 0) { }
            __threadfence();
        }
        __syncthreads();
    }

    int off = g_bsum[b];
    int r = excl + off;
    if (base + 0 < n) { g_rows[base + 0] = r; g_cur[base + 0] = r; g_cnt[base + 0] = 0; r += v0; }
    if (base + 1 < n) { g_rows[base + 1] = r; g_cur[base + 1] = r; g_cnt[base + 1] = 0; r += v1; }
    if (base + 2 < n) { g_rows[base + 2] = r; g_cur[base + 2] = r; g_cnt[base + 2] = 0; r += v2; }
    if (base + 3 < n) { g_rows[base + 3] = r; g_cur[base + 3] = r; g_cnt[base + 3] = 0; }

    __syncthreads();
    if (t == 0) {
        int d = atomicAdd((int*)&g_done, 1);
        if (d == nb - 1) { g_bar = 0; g_flag = 0; g_done = 0; }
    }
}

// ---------------- CSR fill ----------------

__global__ void k_fill(const int* __restrict__ src, const int* __restrict__ dst, int e) {
    int i = blockIdx.x * blockDim.x + threadIdx.x;
    if (i >= e) return;
    int s = src[i], d = dst[i];
    int pos = atomicAdd(&g_cur[d], 1);
    g_esrc[pos] = s;
}

// ---------------- agg layer 1 + fused layer-2 transform (R6 config, 37us) ----
// 4 lanes per node; lane c owns feats [4c,4c+4). dinv[s] gathered from L2.

__global__ __launch_bounds__(TPB) void k_agg1(const float* __restrict__ b1,
                                              const float* __restrict__ W2, int n) {
    __shared__ float sW2[HD * 8];
    __shared__ float sb1[HD];
    int t = threadIdx.x;
    if (t < HD * 8) {
        int j = t >> 3, cc = t & 7;
        sW2[t] = (cc < CD) ? W2[j * CD + cc] : 0.f;
    } else if (t < HD * 8 + HD) {
        sb1[t - HD * 8] = b1[t - HD * 8];
    }
    __syncthreads();

    int node = blockIdx.x * 64 + (t >> 2);
    int c = t & 3;
    bool valid = node < n;
    if (!valid) node = n - 1;

    float dv = g_dinv[node];
    float4 h = *(const float4*)(g_h1 + (size_t)node * HD + c * 4);
    float4 acc = make_float4(h.x * dv, h.y * dv, h.z * dv, h.w * dv);

    int st = g_rows[node];
    int cnt = g_rows[node + 1] - st;
    int j = 0;
    for (; j + 1 < cnt; j += 2) {
        int s0 = g_esrc[st + j], s1 = g_esrc[st + j + 1];
        float m0 = g_dinv[s0],   m1 = g_dinv[s1];
        float4 w0 = *(const float4*)(g_h1 + (size_t)s0 * HD + c * 4);
        float4 w1 = *(const float4*)(g_h1 + (size_t)s1 * HD + c * 4);
        acc.x += w0.x * m0 + w1.x * m1;
        acc.y += w0.y * m0 + w1.y * m1;
        acc.z += w0.z * m0 + w1.z * m1;
        acc.w += w0.w * m0 + w1.w * m1;
    }
    if (j < cnt) {
        int s0 = g_esrc[st + j];
        float m0 = g_dinv[s0];
        float4 w0 = *(const float4*)(g_h1 + (size_t)s0 * HD + c * 4);
        acc.x += w0.x * m0; acc.y += w0.y * m0;
        acc.z += w0.z * m0; acc.w += w0.w * m0;
    }

    float q0 = fmaxf(acc.x * dv + sb1[c * 4 + 0], 0.f);
    float q1 = fmaxf(acc.y * dv + sb1[c * 4 + 1], 0.f);
    float q2 = fmaxf(acc.z * dv + sb1[c * 4 + 2], 0.f);
    float q3 = fmaxf(acc.w * dv + sb1[c * 4 + 3], 0.f);

    float p[8];
#pragma unroll
    for (int cc = 0; cc < 8; cc++) {
        p[cc] = q0 * sW2[(c * 4 + 0) * 8 + cc]
              + q1 * sW2[(c * 4 + 1) * 8 + cc]
              + q2 * sW2[(c * 4 + 2) * 8 + cc]
              + q3 * sW2[(c * 4 + 3) * 8 + cc];
    }
#pragma unroll
    for (int cc = 0; cc < 8; cc++) {
        p[cc] += __shfl_xor_sync(0xFFFFFFFFu, p[cc], 1);
        p[cc] += __shfl_xor_sync(0xFFFFFFFFu, p[cc], 2);
    }
    if (valid) {
        if (c == 0)
            *(float4*)(g_h2 + (size_t)node * 8)     = make_float4(p[0], p[1], p[2], p[3]);
        else if (c == 1)
            *(float4*)(g_h2 + (size_t)node * 8 + 4) = make_float4(p[4], p[5], p[6], 0.f);
    }
}

// ---------------- agg layer 2 + fused bias + log_softmax ----------------

__global__ __launch_bounds__(TPB) void k_agg2(const float* __restrict__ b2,
                                              float* __restrict__ out, int n) {
    __shared__ float sb2[8];
    int t = threadIdx.x;
    if (t < 8) sb2[t] = (t < CD) ? b2[t] : -1e30f;   // pad lane -> exp()==0
    __syncthreads();

    int node = blockIdx.x * 128 + (t >> 1);
    int c = t & 1;
    bool valid = node < n;
    if (!valid) node = n - 1;

    float dv = g_dinv[node];
    float4 h = *(const float4*)(g_h2 + (size_t)node * 8 + c * 4);
    float4 acc = make_float4(h.x * dv, h.y * dv, h.z * dv, h.w * dv);

    int st = g_rows[node];
    int cnt = g_rows[node + 1] - st;
    int j = 0;
    for (; j + 1 < cnt; j += 2) {
        int s0 = g_esrc[st + j], s1 = g_esrc[st + j + 1];
        float m0 = g_dinv[s0],   m1 = g_dinv[s1];
        float4 w0 = *(const float4*)(g_h2 + (size_t)s0 * 8 + c * 4);
        float4 w1 = *(const float4*)(g_h2 + (size_t)s1 * 8 + c * 4);
        acc.x += w0.x * m0 + w1.x * m1;
        acc.y += w0.y * m0 + w1.y * m1;
        acc.z += w0.z * m0 + w1.z * m1;
        acc.w += w0.w * m0 + w1.w * m1;
    }
    if (j < cnt) {
        int s0 = g_esrc[st + j];
        float m0 = g_dinv[s0];
        float4 w0 = *(const float4*)(g_h2 + (size_t)s0 * 8 + c * 4);
        acc.x += w0.x * m0; acc.y += w0.y * m0;
        acc.z += w0.z * m0; acc.w += w0.w * m0;
    }

    float o0 = acc.x * dv + sb2[c * 4 + 0];
    float o1 = acc.y * dv + sb2[c * 4 + 1];
    float o2 = acc.z * dv + sb2[c * 4 + 2];
    float o3 = acc.w * dv + sb2[c * 4 + 3];

    float m = fmaxf(fmaxf(o0, o1), fmaxf(o2, o3));
    m = fmaxf(m, __shfl_xor_sync(0xFFFFFFFFu, m, 1));
    float s = expf(o0 - m) + expf(o1 - m) + expf(o2 - m) + expf(o3 - m);
    s += __shfl_xor_sync(0xFFFFFFFFu, s, 1);
    float l = m + logf(s);

    if (valid) {
        float* op = out + (size_t)node * CD + c * 4;
        op[0] = o0 - l; op[1] = o1 - l; op[2] = o2 - l;
        if (c == 0) op[3] = o3 - l;
    }
}

// ---------------- launch ----------------

extern "C" void kernel_launch(void* const* d_in, const int* in_sizes, int n_in,
                              void* d_out, int out_size) {
    const float* x  = (const float*)d_in[0];
    const int*   ei = (const int*)  d_in[1];
    const float* W1 = (const float*)d_in[2];
    const float* b1 = (const float*)d_in[3];
    const float* W2 = (const float*)d_in[4];
    const float* b2 = (const float*)d_in[5];

    const int n = in_sizes[0] / FIN;
    const int e = in_sizes[1] / 2;
    const int* src = ei;
    const int* dst = ei + e;

    const int nbScan = (n + 1023) / 1024;  // 98 <= 148 (must stay resident)

    k_gemm1    <<<(n + 255) / 256, TPB>>>(x, W1, n);
    k_cnt      <<<(e + TPB - 1) / TPB, TPB>>>(dst, e);
    k_scan_all <<<nbScan, TPB>>>(n, nbScan);
    k_fill     <<<(e + TPB - 1) / TPB, TPB>>>(src, dst, e);
    k_agg1     <<<(n + 63) / 64, TPB>>>(b1, W2, n);
    k_agg2     <<<(n + 127) / 128, TPB>>>(b2, (float*)d_out, n);
}

// round 10
// speedup vs baseline: 1.5122x; 1.1142x over previous
#include <cuda_runtime.h>
#include <math.h>

#define FIN 512
#define HD  16
#define CD  7
#define NMAX 100000
#define EMAX 3200000
#define TPB  256

// ---------------- scratch (static device globals) ----------------
__device__ int   g_cnt [NMAX];        // in-degree (w/o self-loop); re-zeroed by scan
__device__ int   g_rows[NMAX + 1];    // CSR row starts (+ total at [n])
__device__ int   g_cur [NMAX];        // fill cursor
__device__ int   g_bsum[128];         // scan block sums
__device__ float g_dinv[NMAX];
__device__ int   g_esrc[EMAX];        // CSR: source node per edge slot
__device__ float g_h1  [NMAX * HD];
__device__ float g_h2  [NMAX * 8];    // 7 classes padded to 8 (col7 == 0)
__device__ volatile int g_bar;        // scan barrier arrive counter
__device__ volatile int g_flag;       // scan barrier release flag
__device__ volatile int g_done;       // scan exit counter (self-reset)

// ---------------- side stream / events (created before harness checkpoints) --
static cudaStream_t g_sideStream = 0;
static cudaEvent_t  g_evFork = 0, g_evJoin = 0;
namespace {
struct StreamInit {
    StreamInit() {
        cudaStreamCreateWithFlags(&g_sideStream, cudaStreamNonBlocking);
        cudaEventCreateWithFlags(&g_evFork, cudaEventDisableTiming);
        cudaEventCreateWithFlags(&g_evJoin, cudaEventDisableTiming);
    }
};
StreamInit g_streamInit;
}

// ---------------- GEMM1: h1 = x @ W1 (exact round-1 kernel, 68.8us measured) ----

__global__ __launch_bounds__(256) void k_gemm1(const float* __restrict__ x,
                                               const float* __restrict__ W1, int n) {
    __shared__ float4 sW[32 * 4];        // 32 k x 16 j
    __shared__ float  sX[256 * 33];      // 256 nodes x 32 k (+1 pad)

    const int t  = threadIdx.x;
    const int n0 = blockIdx.x * 256;
    const int ng = t >> 2;               // 0..63
    const int jg = t & 3;                // 0..3

    float acc[4][4];
#pragma unroll
    for (int a = 0; a < 4; a++)
#pragma unroll
        for (int b = 0; b < 4; b++) acc[a][b] = 0.0f;

    for (int k0 = 0; k0 < FIN; k0 += 32) {
        __syncthreads();
        if (t < 128) {
            sW[t] = *(const float4*)(W1 + (size_t)(k0 + (t >> 2)) * HD + (t & 3) * 4);
        }
#pragma unroll
        for (int i = 0; i < 8; i++) {
            int f    = t + 256 * i;
            int nl   = f >> 3;
            int kq   = f & 7;
            int node = n0 + nl;
            float4 v = make_float4(0.f, 0.f, 0.f, 0.f);
            if (node < n) v = *(const float4*)(x + (size_t)node * FIN + k0 + kq * 4);
            float* sp = &sX[nl * 33 + kq * 4];
            sp[0] = v.x; sp[1] = v.y; sp[2] = v.z; sp[3] = v.w;
        }
        __syncthreads();
#pragma unroll
        for (int k = 0; k < 32; k++) {
            float4 wv = sW[k * 4 + jg];
            float x0 = sX[(ng * 4 + 0) * 33 + k];
            float x1 = sX[(ng * 4 + 1) * 33 + k];
            float x2 = sX[(ng * 4 + 2) * 33 + k];
            float x3 = sX[(ng * 4 + 3) * 33 + k];
            acc[0][0] += x0 * wv.x; acc[0][1] += x0 * wv.y; acc[0][2] += x0 * wv.z; acc[0][3] += x0 * wv.w;
            acc[1][0] += x1 * wv.x; acc[1][1] += x1 * wv.y; acc[1][2] += x1 * wv.z; acc[1][3] += x1 * wv.w;
            acc[2][0] += x2 * wv.x; acc[2][1] += x2 * wv.y; acc[2][2] += x2 * wv.z; acc[2][3] += x2 * wv.w;
            acc[3][0] += x3 * wv.x; acc[3][1] += x3 * wv.y; acc[3][2] += x3 * wv.z; acc[3][3] += x3 * wv.w;
        }
    }
#pragma unroll
    for (int ni = 0; ni < 4; ni++) {
        int node = n0 + ng * 4 + ni;
        if (node < n)
            *(float4*)&g_h1[(size_t)node * HD + jg * 4] =
                make_float4(acc[ni][0], acc[ni][1], acc[ni][2], acc[ni][3]);
    }
}

// ---------------- degree count: 4 edges/thread for MLP ----------------

__global__ void k_cnt(const int* __restrict__ dst, int e) {
    int i = (blockIdx.x * blockDim.x + threadIdx.x) * 4;
    if (i + 3 < e) {
        int d0 = dst[i], d1 = dst[i + 1], d2 = dst[i + 2], d3 = dst[i + 3];
        atomicAdd(&g_cnt[d0], 1);
        atomicAdd(&g_cnt[d1], 1);
        atomicAdd(&g_cnt[d2], 1);
        atomicAdd(&g_cnt[d3], 1);
    } else {
        for (; i < e; i++) atomicAdd(&g_cnt[dst[i]], 1);
    }
}

// ---------------- single-kernel scan (+rsqrt, +cnt re-zero, self-reset) ------
// Grid must be <= 148 blocks. nb = ceil(n/1024) = 98 here. Blocks only wait on
// each other; anything co-resident retires independently -> no deadlock.

__global__ __launch_bounds__(TPB) void k_scan_all(int n, int nb) {
    __shared__ int s[256];
    const int t = threadIdx.x;
    const int b = blockIdx.x;

    int base = b * 1024 + t * 4;
    int v0 = (base + 0 < n) ? g_cnt[base + 0] : 0;
    int v1 = (base + 1 < n) ? g_cnt[base + 1] : 0;
    int v2 = (base + 2 < n) ? g_cnt[base + 2] : 0;
    int v3 = (base + 3 < n) ? g_cnt[base + 3] : 0;
    if (base + 0 < n) g_dinv[base + 0] = rsqrtf((float)(v0 + 1));
    if (base + 1 < n) g_dinv[base + 1] = rsqrtf((float)(v1 + 1));
    if (base + 2 < n) g_dinv[base + 2] = rsqrtf((float)(v2 + 1));
    if (base + 3 < n) g_dinv[base + 3] = rsqrtf((float)(v3 + 1));
    int ts = v0 + v1 + v2 + v3;
    s[t] = ts;
    __syncthreads();
#pragma unroll
    for (int off = 1; off < 256; off <<= 1) {
        int xv = (t >= off) ? s[t - off] : 0;
        __syncthreads();
        s[t] += xv;
        __syncthreads();
    }
    int excl = s[t] - ts;

    if (t == 255) {
        g_bsum[b] = s[255];
        __threadfence();
        atomicAdd((int*)&g_bar, 1);
    }
    __syncthreads();

    if (b == 0) {
        if (t == 0) {
            while (g_bar < nb) { __nanosleep(64); }
        }
        __syncthreads();
        // parallel scan of block sums in smem
        int v = (t < nb) ? g_bsum[t] : 0;
        s[t] = v;
        __syncthreads();
#pragma unroll
        for (int off = 1; off < 256; off <<= 1) {
            int xv = (t >= off) ? s[t - off] : 0;
            __syncthreads();
            s[t] += xv;
            __syncthreads();
        }
        if (t < nb) g_bsum[t] = s[t] - v;   // exclusive
        if (t == 255) g_rows[n] = s[255];   // total edges
        __threadfence();
        __syncthreads();
        if (t == 0) g_flag = 1;
    } else {
        if (t == 0) {
            while (g_flag == 0) { __nanosleep(64); }
            __threadfence();
        }
        __syncthreads();
    }

    int off = g_bsum[b];
    int r = excl + off;
    if (base + 0 < n) { g_rows[base + 0] = r; g_cur[base + 0] = r; g_cnt[base + 0] = 0; r += v0; }
    if (base + 1 < n) { g_rows[base + 1] = r; g_cur[base + 1] = r; g_cnt[base + 1] = 0; r += v1; }
    if (base + 2 < n) { g_rows[base + 2] = r; g_cur[base + 2] = r; g_cnt[base + 2] = 0; r += v2; }
    if (base + 3 < n) { g_rows[base + 3] = r; g_cur[base + 3] = r; g_cnt[base + 3] = 0; }

    __syncthreads();
    if (t == 0) {
        int d = atomicAdd((int*)&g_done, 1);
        if (d == nb - 1) { g_bar = 0; g_flag = 0; g_done = 0; }
    }
}

// ---------------- CSR fill: 4 edges/thread for MLP ----------------

__global__ void k_fill(const int* __restrict__ src, const int* __restrict__ dst, int e) {
    int i = (blockIdx.x * blockDim.x + threadIdx.x) * 4;
    if (i + 3 < e) {
        int s0 = src[i], s1 = src[i + 1], s2 = src[i + 2], s3 = src[i + 3];
        int d0 = dst[i], d1 = dst[i + 1], d2 = dst[i + 2], d3 = dst[i + 3];
        int p0 = atomicAdd(&g_cur[d0], 1);
        int p1 = atomicAdd(&g_cur[d1], 1);
        int p2 = atomicAdd(&g_cur[d2], 1);
        int p3 = atomicAdd(&g_cur[d3], 1);
        g_esrc[p0] = s0; g_esrc[p1] = s1; g_esrc[p2] = s2; g_esrc[p3] = s3;
    } else {
        for (; i < e; i++) {
            int pos = atomicAdd(&g_cur[dst[i]], 1);
            g_esrc[pos] = src[i];
        }
    }
}

// ---------------- agg layer 1 + fused layer-2 transform (R6 config) ----------

__global__ __launch_bounds__(TPB) void k_agg1(const float* __restrict__ b1,
                                              const float* __restrict__ W2, int n) {
    __shared__ float sW2[HD * 8];
    __shared__ float sb1[HD];
    int t = threadIdx.x;
    if (t < HD * 8) {
        int j = t >> 3, cc = t & 7;
        sW2[t] = (cc < CD) ? W2[j * CD + cc] : 0.f;
    } else if (t < HD * 8 + HD) {
        sb1[t - HD * 8] = b1[t - HD * 8];
    }
    __syncthreads();

    int node = blockIdx.x * 64 + (t >> 2);
    int c = t & 3;
    bool valid = node < n;
    if (!valid) node = n - 1;

    float dv = g_dinv[node];
    float4 h = *(const float4*)(g_h1 + (size_t)node * HD + c * 4);
    float4 acc = make_float4(h.x * dv, h.y * dv, h.z * dv, h.w * dv);

    int st = g_rows[node];
    int cnt = g_rows[node + 1] - st;
    int j = 0;
    for (; j + 1 < cnt; j += 2) {
        int s0 = g_esrc[st + j], s1 = g_esrc[st + j + 1];
        float m0 = g_dinv[s0],   m1 = g_dinv[s1];
        float4 w0 = *(const float4*)(g_h1 + (size_t)s0 * HD + c * 4);
        float4 w1 = *(const float4*)(g_h1 + (size_t)s1 * HD + c * 4);
        acc.x += w0.x * m0 + w1.x * m1;
        acc.y += w0.y * m0 + w1.y * m1;
        acc.z += w0.z * m0 + w1.z * m1;
        acc.w += w0.w * m0 + w1.w * m1;
    }
    if (j < cnt) {
        int s0 = g_esrc[st + j];
        float m0 = g_dinv[s0];
        float4 w0 = *(const float4*)(g_h1 + (size_t)s0 * HD + c * 4);
        acc.x += w0.x * m0; acc.y += w0.y * m0;
        acc.z += w0.z * m0; acc.w += w0.w * m0;
    }

    float q0 = fmaxf(acc.x * dv + sb1[c * 4 + 0], 0.f);
    float q1 = fmaxf(acc.y * dv + sb1[c * 4 + 1], 0.f);
    float q2 = fmaxf(acc.z * dv + sb1[c * 4 + 2], 0.f);
    float q3 = fmaxf(acc.w * dv + sb1[c * 4 + 3], 0.f);

    float p[8];
#pragma unroll
    for (int cc = 0; cc < 8; cc++) {
        p[cc] = q0 * sW2[(c * 4 + 0) * 8 + cc]
              + q1 * sW2[(c * 4 + 1) * 8 + cc]
              + q2 * sW2[(c * 4 + 2) * 8 + cc]
              + q3 * sW2[(c * 4 + 3) * 8 + cc];
    }
#pragma unroll
    for (int cc = 0; cc < 8; cc++) {
        p[cc] += __shfl_xor_sync(0xFFFFFFFFu, p[cc], 1);
        p[cc] += __shfl_xor_sync(0xFFFFFFFFu, p[cc], 2);
    }
    if (valid) {
        if (c == 0)
            *(float4*)(g_h2 + (size_t)node * 8)     = make_float4(p[0], p[1], p[2], p[3]);
        else if (c == 1)
            *(float4*)(g_h2 + (size_t)node * 8 + 4) = make_float4(p[4], p[5], p[6], 0.f);
    }
}

// ---------------- agg layer 2 + fused bias + log_softmax ----------------

__global__ __launch_bounds__(TPB) void k_agg2(const float* __restrict__ b2,
                                              float* __restrict__ out, int n) {
    __shared__ float sb2[8];
    int t = threadIdx.x;
    if (t < 8) sb2[t] = (t < CD) ? b2[t] : -1e30f;   // pad lane -> exp()==0
    __syncthreads();

    int node = blockIdx.x * 128 + (t >> 1);
    int c = t & 1;
    bool valid = node < n;
    if (!valid) node = n - 1;

    float dv = g_dinv[node];
    float4 h = *(const float4*)(g_h2 + (size_t)node * 8 + c * 4);
    float4 acc = make_float4(h.x * dv, h.y * dv, h.z * dv, h.w * dv);

    int st = g_rows[node];
    int cnt = g_rows[node + 1] - st;
    int j = 0;
    for (; j + 1 < cnt; j += 2) {
        int s0 = g_esrc[st + j], s1 = g_esrc[st + j + 1];
        float m0 = g_dinv[s0],   m1 = g_dinv[s1];
        float4 w0 = *(const float4*)(g_h2 + (size_t)s0 * 8 + c * 4);
        float4 w1 = *(const float4*)(g_h2 + (size_t)s1 * 8 + c * 4);
        acc.x += w0.x * m0 + w1.x * m1;
        acc.y += w0.y * m0 + w1.y * m1;
        acc.z += w0.z * m0 + w1.z * m1;
        acc.w += w0.w * m0 + w1.w * m1;
    }
    if (j < cnt) {
        int s0 = g_esrc[st + j];
        float m0 = g_dinv[s0];
        float4 w0 = *(const float4*)(g_h2 + (size_t)s0 * 8 + c * 4);
        acc.x += w0.x * m0; acc.y += w0.y * m0;
        acc.z += w0.z * m0; acc.w += w0.w * m0;
    }

    float o0 = acc.x * dv + sb2[c * 4 + 0];
    float o1 = acc.y * dv + sb2[c * 4 + 1];
    float o2 = acc.z * dv + sb2[c * 4 + 2];
    float o3 = acc.w * dv + sb2[c * 4 + 3];

    float m = fmaxf(fmaxf(o0, o1), fmaxf(o2, o3));
    m = fmaxf(m, __shfl_xor_sync(0xFFFFFFFFu, m, 1));
    float s = expf(o0 - m) + expf(o1 - m) + expf(o2 - m) + expf(o3 - m);
    s += __shfl_xor_sync(0xFFFFFFFFu, s, 1);
    float l = m + logf(s);

    if (valid) {
        float* op = out + (size_t)node * CD + c * 4;
        op[0] = o0 - l; op[1] = o1 - l; op[2] = o2 - l;
        if (c == 0) op[3] = o3 - l;
    }
}

// ---------------- launch: GEMM on main stream || CSR chain on side stream ----

extern "C" void kernel_launch(void* const* d_in, const int* in_sizes, int n_in,
                              void* d_out, int out_size) {
    const float* x  = (const float*)d_in[0];
    const int*   ei = (const int*)  d_in[1];
    const float* W1 = (const float*)d_in[2];
    const float* b1 = (const float*)d_in[3];
    const float* W2 = (const float*)d_in[4];
    const float* b2 = (const float*)d_in[5];

    const int n = in_sizes[0] / FIN;
    const int e = in_sizes[1] / 2;
    const int* src = ei;
    const int* dst = ei + e;

    const int nbScan = (n + 1023) / 1024;  // 98 <= 148 (must stay resident)
    const int nbE4   = (e / 4 + TPB - 1) / TPB + 1;

    // fork: side stream handles the CSR build while main stream runs the GEMM
    cudaEventRecord(g_evFork, 0);
    cudaStreamWaitEvent(g_sideStream, g_evFork, 0);

    k_cnt      <<<nbE4, TPB, 0, g_sideStream>>>(dst, e);
    k_scan_all <<<nbScan, TPB, 0, g_sideStream>>>(n, nbScan);
    k_fill     <<<nbE4, TPB, 0, g_sideStream>>>(src, dst, e);
    cudaEventRecord(g_evJoin, g_sideStream);

    k_gemm1    <<<(n + 255) / 256, TPB>>>(x, W1, n);

    // join: aggregation needs both h1 (main) and the CSR (side)
    cudaStreamWaitEvent(0, g_evJoin, 0);
    k_agg1     <<<(n + 63) / 64, TPB>>>(b1, W2, n);
    k_agg2     <<<(n + 127) / 128, TPB>>>(b2, (float*)d_out, n);
}

// round 11
// speedup vs baseline: 1.5506x; 1.0254x over previous
#include <cuda_runtime.h>
#include <math.h>

#define FIN 512
#define HD  16
#define CD  7
#define NMAX 100000
#define EMAX 3200000
#define TPB  256

// ---------------- scratch (static device globals) ----------------
__device__ int   g_cnt [NMAX];        // in-degree (w/o self-loop); re-zeroed by scan
__device__ int   g_rows[NMAX + 1];    // CSR row starts (+ total at [n])
__device__ int   g_cur [NMAX];        // fill cursor
__device__ int   g_bsum[128];         // scan block sums
__device__ float g_dinv[NMAX];
__device__ int2  g_edge[EMAX];        // CSR: {src, bitcast(dinv[src])}
__device__ float g_h1  [NMAX * HD];
__device__ float g_h2  [NMAX * 8];    // 7 classes padded to 8 (col7 == 0)
__device__ volatile int g_bar;        // scan barrier arrive counter
__device__ volatile int g_flag;       // scan barrier release flag
__device__ volatile int g_done;       // scan exit counter (self-reset)

// ---------------- side stream / events (created before harness checkpoints) --
static cudaStream_t g_sideStream = 0;
static cudaEvent_t  g_evFork = 0, g_evJoin = 0;
namespace {
struct StreamInit {
    StreamInit() {
        cudaStreamCreateWithFlags(&g_sideStream, cudaStreamNonBlocking);
        cudaEventCreateWithFlags(&g_evFork, cudaEventDisableTiming);
        cudaEventCreateWithFlags(&g_evJoin, cudaEventDisableTiming);
    }
};
StreamInit g_streamInit;
}

// ---------------- GEMM1: h1 = x @ W1 (exact round-1 kernel, 69us measured) ----

__global__ __launch_bounds__(256) void k_gemm1(const float* __restrict__ x,
                                               const float* __restrict__ W1, int n) {
    __shared__ float4 sW[32 * 4];        // 32 k x 16 j
    __shared__ float  sX[256 * 33];      // 256 nodes x 32 k (+1 pad)

    const int t  = threadIdx.x;
    const int n0 = blockIdx.x * 256;
    const int ng = t >> 2;               // 0..63
    const int jg = t & 3;                // 0..3

    float acc[4][4];
#pragma unroll
    for (int a = 0; a < 4; a++)
#pragma unroll
        for (int b = 0; b < 4; b++) acc[a][b] = 0.0f;

    for (int k0 = 0; k0 < FIN; k0 += 32) {
        __syncthreads();
        if (t < 128) {
            sW[t] = *(const float4*)(W1 + (size_t)(k0 + (t >> 2)) * HD + (t & 3) * 4);
        }
#pragma unroll
        for (int i = 0; i < 8; i++) {
            int f    = t + 256 * i;
            int nl   = f >> 3;
            int kq   = f & 7;
            int node = n0 + nl;
            float4 v = make_float4(0.f, 0.f, 0.f, 0.f);
            if (node < n) v = *(const float4*)(x + (size_t)node * FIN + k0 + kq * 4);
            float* sp = &sX[nl * 33 + kq * 4];
            sp[0] = v.x; sp[1] = v.y; sp[2] = v.z; sp[3] = v.w;
        }
        __syncthreads();
#pragma unroll
        for (int k = 0; k < 32; k++) {
            float4 wv = sW[k * 4 + jg];
            float x0 = sX[(ng * 4 + 0) * 33 + k];
            float x1 = sX[(ng * 4 + 1) * 33 + k];
            float x2 = sX[(ng * 4 + 2) * 33 + k];
            float x3 = sX[(ng * 4 + 3) * 33 + k];
            acc[0][0] += x0 * wv.x; acc[0][1] += x0 * wv.y; acc[0][2] += x0 * wv.z; acc[0][3] += x0 * wv.w;
            acc[1][0] += x1 * wv.x; acc[1][1] += x1 * wv.y; acc[1][2] += x1 * wv.z; acc[1][3] += x1 * wv.w;
            acc[2][0] += x2 * wv.x; acc[2][1] += x2 * wv.y; acc[2][2] += x2 * wv.z; acc[2][3] += x2 * wv.w;
            acc[3][0] += x3 * wv.x; acc[3][1] += x3 * wv.y; acc[3][2] += x3 * wv.z; acc[3][3] += x3 * wv.w;
        }
    }
#pragma unroll
    for (int ni = 0; ni < 4; ni++) {
        int node = n0 + ng * 4 + ni;
        if (node < n)
            *(float4*)&g_h1[(size_t)node * HD + jg * 4] =
                make_float4(acc[ni][0], acc[ni][1], acc[ni][2], acc[ni][3]);
    }
}

// ---------------- degree count: 4 edges/thread for MLP ----------------

__global__ void k_cnt(const int* __restrict__ dst, int e) {
    int i = (blockIdx.x * blockDim.x + threadIdx.x) * 4;
    if (i + 3 < e) {
        int d0 = dst[i], d1 = dst[i + 1], d2 = dst[i + 2], d3 = dst[i + 3];
        atomicAdd(&g_cnt[d0], 1);
        atomicAdd(&g_cnt[d1], 1);
        atomicAdd(&g_cnt[d2], 1);
        atomicAdd(&g_cnt[d3], 1);
    } else {
        for (; i < e; i++) atomicAdd(&g_cnt[dst[i]], 1);
    }
}

// ---------------- single-kernel scan (+rsqrt, +cnt re-zero, self-reset) ------
// Grid must be <= 148 blocks. nb = ceil(n/1024) = 98 here.

__global__ __launch_bounds__(TPB) void k_scan_all(int n, int nb) {
    __shared__ int s[256];
    const int t = threadIdx.x;
    const int b = blockIdx.x;

    int base = b * 1024 + t * 4;
    int v0 = (base + 0 < n) ? g_cnt[base + 0] : 0;
    int v1 = (base + 1 < n) ? g_cnt[base + 1] : 0;
    int v2 = (base + 2 < n) ? g_cnt[base + 2] : 0;
    int v3 = (base + 3 < n) ? g_cnt[base + 3] : 0;
    if (base + 0 < n) g_dinv[base + 0] = rsqrtf((float)(v0 + 1));
    if (base + 1 < n) g_dinv[base + 1] = rsqrtf((float)(v1 + 1));
    if (base + 2 < n) g_dinv[base + 2] = rsqrtf((float)(v2 + 1));
    if (base + 3 < n) g_dinv[base + 3] = rsqrtf((float)(v3 + 1));
    int ts = v0 + v1 + v2 + v3;
    s[t] = ts;
    __syncthreads();
#pragma unroll
    for (int off = 1; off < 256; off <<= 1) {
        int xv = (t >= off) ? s[t - off] : 0;
        __syncthreads();
        s[t] += xv;
        __syncthreads();
    }
    int excl = s[t] - ts;

    if (t == 255) {
        g_bsum[b] = s[255];
        __threadfence();
        atomicAdd((int*)&g_bar, 1);
    }
    __syncthreads();

    if (b == 0) {
        if (t == 0) {
            while (g_bar < nb) { __nanosleep(64); }
        }
        __syncthreads();
        int v = (t < nb) ? g_bsum[t] : 0;
        s[t] = v;
        __syncthreads();
#pragma unroll
        for (int off = 1; off < 256; off <<= 1) {
            int xv = (t >= off) ? s[t - off] : 0;
            __syncthreads();
            s[t] += xv;
            __syncthreads();
        }
        if (t < nb) g_bsum[t] = s[t] - v;   // exclusive
        if (t == 255) g_rows[n] = s[255];   // total edges
        __threadfence();
        __syncthreads();
        if (t == 0) g_flag = 1;
    } else {
        if (t == 0) {
            while (g_flag == 0) { __nanosleep(64); }
            __threadfence();
        }
        __syncthreads();
    }

    int off = g_bsum[b];
    int r = excl + off;
    if (base + 0 < n) { g_rows[base + 0] = r; g_cur[base + 0] = r; g_cnt[base + 0] = 0; r += v0; }
    if (base + 1 < n) { g_rows[base + 1] = r; g_cur[base + 1] = r; g_cnt[base + 1] = 0; r += v1; }
    if (base + 2 < n) { g_rows[base + 2] = r; g_cur[base + 2] = r; g_cnt[base + 2] = 0; r += v2; }
    if (base + 3 < n) { g_rows[base + 3] = r; g_cur[base + 3] = r; g_cnt[base + 3] = 0; }

    __syncthreads();
    if (t == 0) {
        int d = atomicAdd((int*)&g_done, 1);
        if (d == nb - 1) { g_bar = 0; g_flag = 0; g_done = 0; }
    }
}

// ---------------- CSR fill: writes {src, dinv[src]} (kills agg's dinv gather) --
// Runs after scan on the side stream, so g_dinv is ready.

__global__ void k_fill(const int* __restrict__ src, const int* __restrict__ dst, int e) {
    int i = (blockIdx.x * blockDim.x + threadIdx.x) * 4;
    if (i + 3 < e) {
        int s0 = src[i], s1 = src[i + 1], s2 = src[i + 2], s3 = src[i + 3];
        int d0 = dst[i], d1 = dst[i + 1], d2 = dst[i + 2], d3 = dst[i + 3];
        float m0 = g_dinv[s0], m1 = g_dinv[s1], m2 = g_dinv[s2], m3 = g_dinv[s3];
        int p0 = atomicAdd(&g_cur[d0], 1);
        int p1 = atomicAdd(&g_cur[d1], 1);
        int p2 = atomicAdd(&g_cur[d2], 1);
        int p3 = atomicAdd(&g_cur[d3], 1);
        g_edge[p0] = make_int2(s0, __float_as_int(m0));
        g_edge[p1] = make_int2(s1, __float_as_int(m1));
        g_edge[p2] = make_int2(s2, __float_as_int(m2));
        g_edge[p3] = make_int2(s3, __float_as_int(m3));
    } else {
        for (; i < e; i++) {
            int s = src[i];
            int pos = atomicAdd(&g_cur[dst[i]], 1);
            g_edge[pos] = make_int2(s, __float_as_int(g_dinv[s]));
        }
    }
}

// ---------------- agg layer 1 + fused layer-2 transform ----------------
// 4 lanes per node; lane c owns feats [4c,4c+4). 2-level load chain: edge -> h1.

__global__ __launch_bounds__(TPB) void k_agg1(const float* __restrict__ b1,
                                              const float* __restrict__ W2, int n) {
    __shared__ float sW2[HD * 8];
    __shared__ float sb1[HD];
    int t = threadIdx.x;
    if (t < HD * 8) {
        int j = t >> 3, cc = t & 7;
        sW2[t] = (cc < CD) ? W2[j * CD + cc] : 0.f;
    } else if (t < HD * 8 + HD) {
        sb1[t - HD * 8] = b1[t - HD * 8];
    }
    __syncthreads();

    int node = blockIdx.x * 64 + (t >> 2);
    int c = t & 3;
    bool valid = node < n;
    if (!valid) node = n - 1;

    float dv = g_dinv[node];
    float4 h = *(const float4*)(g_h1 + (size_t)node * HD + c * 4);
    float4 acc = make_float4(h.x * dv, h.y * dv, h.z * dv, h.w * dv);

    int st = g_rows[node];
    int cnt = g_rows[node + 1] - st;
    int j = 0;
    for (; j + 1 < cnt; j += 2) {
        int2 e0 = g_edge[st + j], e1 = g_edge[st + j + 1];
        float m0 = __int_as_float(e0.y), m1 = __int_as_float(e1.y);
        float4 w0 = *(const float4*)(g_h1 + (size_t)e0.x * HD + c * 4);
        float4 w1 = *(const float4*)(g_h1 + (size_t)e1.x * HD + c * 4);
        acc.x += w0.x * m0 + w1.x * m1;
        acc.y += w0.y * m0 + w1.y * m1;
        acc.z += w0.z * m0 + w1.z * m1;
        acc.w += w0.w * m0 + w1.w * m1;
    }
    if (j < cnt) {
        int2 e0 = g_edge[st + j];
        float m0 = __int_as_float(e0.y);
        float4 w0 = *(const float4*)(g_h1 + (size_t)e0.x * HD + c * 4);
        acc.x += w0.x * m0; acc.y += w0.y * m0;
        acc.z += w0.z * m0; acc.w += w0.w * m0;
    }

    float q0 = fmaxf(acc.x * dv + sb1[c * 4 + 0], 0.f);
    float q1 = fmaxf(acc.y * dv + sb1[c * 4 + 1], 0.f);
    float q2 = fmaxf(acc.z * dv + sb1[c * 4 + 2], 0.f);
    float q3 = fmaxf(acc.w * dv + sb1[c * 4 + 3], 0.f);

    float p[8];
#pragma unroll
    for (int cc = 0; cc < 8; cc++) {
        p[cc] = q0 * sW2[(c * 4 + 0) * 8 + cc]
              + q1 * sW2[(c * 4 + 1) * 8 + cc]
              + q2 * sW2[(c * 4 + 2) * 8 + cc]
              + q3 * sW2[(c * 4 + 3) * 8 + cc];
    }
#pragma unroll
    for (int cc = 0; cc < 8; cc++) {
        p[cc] += __shfl_xor_sync(0xFFFFFFFFu, p[cc], 1);
        p[cc] += __shfl_xor_sync(0xFFFFFFFFu, p[cc], 2);
    }
    if (valid) {
        if (c == 0)
            *(float4*)(g_h2 + (size_t)node * 8)     = make_float4(p[0], p[1], p[2], p[3]);
        else if (c == 1)
            *(float4*)(g_h2 + (size_t)node * 8 + 4) = make_float4(p[4], p[5], p[6], 0.f);
    }
}

// ---------------- agg layer 2 + fused bias + log_softmax ----------------

__global__ __launch_bounds__(TPB) void k_agg2(const float* __restrict__ b2,
                                              float* __restrict__ out, int n) {
    __shared__ float sb2[8];
    int t = threadIdx.x;
    if (t < 8) sb2[t] = (t < CD) ? b2[t] : -1e30f;   // pad lane -> exp()==0
    __syncthreads();

    int node = blockIdx.x * 128 + (t >> 1);
    int c = t & 1;
    bool valid = node < n;
    if (!valid) node = n - 1;

    float dv = g_dinv[node];
    float4 h = *(const float4*)(g_h2 + (size_t)node * 8 + c * 4);
    float4 acc = make_float4(h.x * dv, h.y * dv, h.z * dv, h.w * dv);

    int st = g_rows[node];
    int cnt = g_rows[node + 1] - st;
    int j = 0;
    for (; j + 1 < cnt; j += 2) {
        int2 e0 = g_edge[st + j], e1 = g_edge[st + j + 1];
        float m0 = __int_as_float(e0.y), m1 = __int_as_float(e1.y);
        float4 w0 = *(const float4*)(g_h2 + (size_t)e0.x * 8 + c * 4);
        float4 w1 = *(const float4*)(g_h2 + (size_t)e1.x * 8 + c * 4);
        acc.x += w0.x * m0 + w1.x * m1;
        acc.y += w0.y * m0 + w1.y * m1;
        acc.z += w0.z * m0 + w1.z * m1;
        acc.w += w0.w * m0 + w1.w * m1;
    }
    if (j < cnt) {
        int2 e0 = g_edge[st + j];
        float m0 = __int_as_float(e0.y);
        float4 w0 = *(const float4*)(g_h2 + (size_t)e0.x * 8 + c * 4);
        acc.x += w0.x * m0; acc.y += w0.y * m0;
        acc.z += w0.z * m0; acc.w += w0.w * m0;
    }

    float o0 = acc.x * dv + sb2[c * 4 + 0];
    float o1 = acc.y * dv + sb2[c * 4 + 1];
    float o2 = acc.z * dv + sb2[c * 4 + 2];
    float o3 = acc.w * dv + sb2[c * 4 + 3];

    float m = fmaxf(fmaxf(o0, o1), fmaxf(o2, o3));
    m = fmaxf(m, __shfl_xor_sync(0xFFFFFFFFu, m, 1));
    float s = expf(o0 - m) + expf(o1 - m) + expf(o2 - m) + expf(o3 - m);
    s += __shfl_xor_sync(0xFFFFFFFFu, s, 1);
    float l = m + logf(s);

    if (valid) {
        float* op = out + (size_t)node * CD + c * 4;
        op[0] = o0 - l; op[1] = o1 - l; op[2] = o2 - l;
        if (c == 0) op[3] = o3 - l;
    }
}

// ---------------- launch: GEMM on main stream || CSR chain on side stream ----

extern "C" void kernel_launch(void* const* d_in, const int* in_sizes, int n_in,
                              void* d_out, int out_size) {
    const float* x  = (const float*)d_in[0];
    const int*   ei = (const int*)  d_in[1];
    const float* W1 = (const float*)d_in[2];
    const float* b1 = (const float*)d_in[3];
    const float* W2 = (const float*)d_in[4];
    const float* b2 = (const float*)d_in[5];

    const int n = in_sizes[0] / FIN;
    const int e = in_sizes[1] / 2;
    const int* src = ei;
    const int* dst = ei + e;

    const int nbScan = (n + 1023) / 1024;  // 98 <= 148 (must stay resident)
    const int nbE4   = (e / 4 + TPB - 1) / TPB + 1;

    // fork: side stream handles the CSR build while main stream runs the GEMM
    cudaEventRecord(g_evFork, 0);
    cudaStreamWaitEvent(g_sideStream, g_evFork, 0);

    k_cnt      <<<nbE4, TPB, 0, g_sideStream>>>(dst, e);
    k_scan_all <<<nbScan, TPB, 0, g_sideStream>>>(n, nbScan);
    k_fill     <<<nbE4, TPB, 0, g_sideStream>>>(src, dst, e);
    cudaEventRecord(g_evJoin, g_sideStream);

    k_gemm1    <<<(n + 255) / 256, TPB>>>(x, W1, n);

    // join: aggregation needs both h1 (main) and the CSR (side)
    cudaStreamWaitEvent(0, g_evJoin, 0);
    k_agg1     <<<(n + 63) / 64, TPB>>>(b1, W2, n);
    k_agg2     <<<(n + 127) / 128, TPB>>>(b2, (float*)d_out, n);
}